// round 10
// baseline (speedup 1.0000x reference)
#include <cuda_runtime.h>
#include <cuda_bf16.h>
#include <cstdint>
#include <math.h>

// Problem constants
#define T_TOK 8192
#define HDIM  1024
#define NEXP  8
#define CAP   4096

// GEMM tiling: CTA 128x128, 8 warps of 32x64, K-chunk 32, 4-stage cp.async
#define TM 128
#define TN 128
#define KC 32
#define NCH 32
#define STAGE_BYTES 16384           // A 8KB + B 8KB (bf16, 64B per 32-k row)
#define SMEM_BYTES (4 * STAGE_BYTES)

// ---------------- scratch (device globals, zero-init at load) ---------------
__device__ int   g_cnt[NEXP];
__device__ int   g_tok[NEXP * CAP];
__device__ float g_wgt[NEXP * CAP];
__device__ uint4 g_xb [(size_t)T_TOK * 128];        // 16MB bf16 permuted x
__device__ uint4 g_w1b[(size_t)NEXP * HDIM * 128];  // 16MB
__device__ uint4 g_w2b[(size_t)NEXP * HDIM * 128];  // 16MB
__device__ uint4 g_h1b[(size_t)NEXP * CAP * 128];   // 64MB bf16 permuted h1

// ---------------- helpers ----------------------------------------------------
__device__ __forceinline__ uint32_t smem_u32(const void* p) {
    uint32_t a;
    asm("{ .reg .u64 t; cvta.to.shared.u64 t, %1; cvt.u32.u64 %0, t; }" : "=r"(a) : "l"(p));
    return a;
}
// pack two fp32 -> bf16x2 (RN); low half = lo
__device__ __forceinline__ uint32_t pack2(float lo, float hi) {
    uint32_t r;
    asm("cvt.rn.bf16x2.f32 %0, %1, %2;" : "=r"(r) : "f"(hi), "f"(lo));
    return r;
}
__device__ __forceinline__ uint4 lds128(uint32_t addr) {
    uint4 v;
    asm volatile("ld.shared.v4.b32 {%0,%1,%2,%3}, [%4];"
                 : "=r"(v.x), "=r"(v.y), "=r"(v.z), "=r"(v.w) : "r"(addr));
    return v;
}
__device__ __forceinline__ void cp16(uint32_t dst, const void* src) {
    asm volatile("cp.async.cg.shared.global [%0], [%1], 16;" :: "r"(dst), "l"(src));
}
#define CP_COMMIT() asm volatile("cp.async.commit_group;" ::: "memory")
#define CP_WAIT2()  asm volatile("cp.async.wait_group 2;" ::: "memory")

__device__ __forceinline__ void mma16(float* c,
    uint32_t a0, uint32_t a1, uint32_t a2, uint32_t a3, uint32_t b0, uint32_t b1)
{
    asm volatile(
        "mma.sync.aligned.m16n8k16.row.col.f32.bf16.bf16.f32 "
        "{%0,%1,%2,%3}, {%4,%5,%6,%7}, {%8,%9}, {%0,%1,%2,%3};"
        : "+f"(c[0]), "+f"(c[1]), "+f"(c[2]), "+f"(c[3])
        : "r"(a0), "r"(a1), "r"(a2), "r"(a3), "r"(b0), "r"(b1));
}

// ---------------- prepass: fp32 -> bf16 permuted rows ------------------------
// Permuted chunk row (64B = 16 bf16-pairs): 16B slot s holds pairs {s,s+4,s+8,s+12}
__global__ __launch_bounds__(256) void prepass(
    const float* __restrict__ x, const float* __restrict__ w1,
    const float* __restrict__ w2)
{
    int which = blockIdx.y;
    const float* src = which == 0 ? x : (which == 1 ? w1 : w2);
    uint4* dst = which == 0 ? g_xb : (which == 1 ? g_w1b : g_w2b);
    int idx = blockIdx.x * 256 + threadIdx.x;   // 8192 rows * 32 chunks
    int row = idx >> 5, c = idx & 31;

    const float4* s4 = (const float4*)(src + (size_t)row * HDIM + c * KC);
    float f[32];
#pragma unroll
    for (int i = 0; i < 8; i++) {
        float4 v = s4[i];
        f[4*i] = v.x; f[4*i+1] = v.y; f[4*i+2] = v.z; f[4*i+3] = v.w;
    }
    uint32_t p[16];
#pragma unroll
    for (int P = 0; P < 16; P++) p[P] = pack2(f[2*P], f[2*P+1]);
    uint4* drow = dst + ((size_t)row * 32 + c) * 4;
#pragma unroll
    for (int s = 0; s < 4; s++)
        drow[s] = make_uint4(p[s], p[s+4], p[s+8], p[s+12]);
}

// ---------------- router ------------------------------------------------------
__global__ __launch_bounds__(256) void router_kernel(
    const float* __restrict__ x, const float* __restrict__ rw,
    float* __restrict__ out, int write_probs)
{
    int t = blockIdx.x * 8 + (threadIdx.x >> 5);
    if (t >= T_TOK) return;
    int lane = threadIdx.x & 31;

    float acc[NEXP];
#pragma unroll
    for (int e = 0; e < NEXP; e++) acc[e] = 0.f;
    const float* xp = x + (size_t)t * HDIM;
    for (int i = lane; i < HDIM; i += 32) {
        float xv = xp[i];
#pragma unroll
        for (int e = 0; e < NEXP; e++)
            acc[e] = fmaf(xv, rw[e * HDIM + i], acc[e]);
    }
#pragma unroll
    for (int e = 0; e < NEXP; e++)
#pragma unroll
        for (int off = 16; off; off >>= 1)
            acc[e] += __shfl_xor_sync(0xffffffffu, acc[e], off);

    if (lane == 0) {
        float m = acc[0];
#pragma unroll
        for (int e = 1; e < NEXP; e++) m = fmaxf(m, acc[e]);
        float p[NEXP]; float s = 0.f;
#pragma unroll
        for (int e = 0; e < NEXP; e++) { p[e] = expf(acc[e] - m); s += p[e]; }
        float inv_s = 1.f / s;
#pragma unroll
        for (int e = 0; e < NEXP; e++) p[e] *= inv_s;

        if (write_probs) {
            float* pr = out + (size_t)T_TOK * HDIM + (size_t)t * NEXP;
#pragma unroll
            for (int e = 0; e < NEXP; e++) pr[e] = p[e];
        }
        int i0 = 0;
#pragma unroll
        for (int e = 1; e < NEXP; e++) if (p[e] > p[i0]) i0 = e;
        int i1 = (i0 == 0) ? 1 : 0;
#pragma unroll
        for (int e = 0; e < NEXP; e++) if (e != i0 && p[e] > p[i1]) i1 = e;

        float v0 = p[i0], v1 = p[i1];
        float invw = 1.f / (v0 + v1);
        int pos0 = atomicAdd(&g_cnt[i0], 1);
        if (pos0 < CAP) { g_tok[i0 * CAP + pos0] = t; g_wgt[i0 * CAP + pos0] = v0 * invw; }
        int pos1 = atomicAdd(&g_cnt[i1], 1);
        if (pos1 < CAP) { g_tok[i1 * CAP + pos1] = t; g_wgt[i1 * CAP + pos1] = v1 * invw; }
    }
}

// ---------------- per-chunk compute: 32x64 warp tile (bf16 HMMA) -------------
// Physical slot of logical slot s in row r is s ^ ((r>>1)&3): conflict-free
// for the warp cp.async STS phases AND all lds128 fragment phases.
__device__ __forceinline__ void compute_chunk(
    uint32_t sbase, float acc[2][8][4], int wm, int wn, int gid, int tig)
{
    uint32_t toff = (uint32_t)((tig ^ ((gid >> 1) & 3)) * 16);
    uint4 alo[2], ahi[2];
#pragma unroll
    for (int mi = 0; mi < 2; mi++) {
        uint32_t a0 = sbase + (wm * 32 + mi * 16 + gid) * 64 + toff;
        alo[mi] = lds128(a0);
        ahi[mi] = lds128(a0 + 8 * 64);
    }
#pragma unroll
    for (int nh = 0; nh < 2; nh++) {
        uint4 fb[4];
#pragma unroll
        for (int ni = 0; ni < 4; ni++) {
            int n = wn * 64 + (nh * 4 + ni) * 8 + gid;
            fb[ni] = lds128(sbase + 8192 + n * 64 + toff);
        }
#pragma unroll
        for (int mi = 0; mi < 2; mi++)
#pragma unroll
            for (int ni = 0; ni < 4; ni++) {
                float* c = acc[mi][nh * 4 + ni];
                mma16(c, alo[mi].x, ahi[mi].x, alo[mi].y, ahi[mi].y, fb[ni].x, fb[ni].y);
                mma16(c, alo[mi].z, ahi[mi].z, alo[mi].w, ahi[mi].w, fb[ni].z, fb[ni].w);
            }
    }
}

// stage chunk cc into buffer buf (thread covers 2 A slots + 2 B slots,
// 32B contiguous gmem per matrix per thread)
#define STAGE(cc, buf) do { \
    uint32_t _b = sb + (uint32_t)(buf) * STAGE_BYTES; \
    const char* _ar = asrc + (cc) * 64; \
    const char* _br = bsrc + (cc) * 64; \
    cp16(_b + aoff0, _ar + s0 * 16); \
    cp16(_b + aoff1, _ar + s1 * 16); \
    cp16(_b + 8192 + aoff0, _br + s0 * 16); \
    cp16(_b + 8192 + aoff1, _br + s1 * 16); \
} while (0)

// ---------------- GEMM1: h1b = relu(xb[gather] @ W1b^T + b1) -----------------
__global__ __launch_bounds__(256, 2) void gemm1_tc(const float* __restrict__ b1)
{
    extern __shared__ char smem[];
    int e = blockIdx.z;
    int count = min(g_cnt[e], CAP);
    int m0 = blockIdx.y * TM;
    if (m0 >= count) return;
    int n0 = blockIdx.x * TN;

    uint32_t sb = smem_u32(smem);
    int tid = threadIdx.x, wid = tid >> 5, lane = tid & 31;
    int wm = wid >> 1, wn = wid & 1, gid = lane >> 2, tig = lane & 3;

    int arow = tid & 127, sh = tid >> 7;
    int s0 = sh * 2, s1 = s0 + 1;
    int sig = (arow >> 1) & 3;
    uint32_t aoff0 = arow * 64 + ((s0 ^ sig) * 16);
    uint32_t aoff1 = arow * 64 + ((s1 ^ sig) * 16);

    int tok = g_tok[e * CAP + m0 + arow];          // stale slots = 0 (zero-init), safe
    const char* asrc = (const char*)g_xb + (size_t)tok * 2048;
    const char* bsrc = (const char*)g_w1b + (size_t)(e * HDIM + n0 + arow) * 2048;

    float acc[2][8][4];
#pragma unroll
    for (int mi = 0; mi < 2; mi++)
#pragma unroll
        for (int ni = 0; ni < 8; ni++)
#pragma unroll
            for (int q = 0; q < 4; q++) acc[mi][ni][q] = 0.f;

    STAGE(0, 0); CP_COMMIT();
    STAGE(1, 1); CP_COMMIT();
    STAGE(2, 2); CP_COMMIT();

    for (int c = 0; c < NCH; c++) {
        CP_WAIT2();
        __syncthreads();
        if (c + 3 < NCH) STAGE(c + 3, (c + 3) & 3);
        CP_COMMIT();
        compute_chunk(sb + (c & 3) * STAGE_BYTES, acc, wm, wn, gid, tig);
    }

    // epilogue: relu(acc + b1) -> g_h1b (bf16, permuted rows)
    const float* bb = b1 + e * HDIM + n0 + wn * 64 + tig * 2;
    float2 bias[8];
#pragma unroll
    for (int ni = 0; ni < 8; ni++) bias[ni] = *(const float2*)(bb + ni * 8);

#pragma unroll
    for (int mi = 0; mi < 2; mi++)
#pragma unroll
        for (int h = 0; h < 2; h++) {
            int r = m0 + wm * 32 + mi * 16 + h * 8 + gid;
            if (r < count) {
                char* rowp = (char*)g_h1b + (size_t)(e * CAP + r) * 2048 + tig * 16;
#pragma unroll
                for (int ch = 0; ch < 2; ch++) {
                    uint4 o;
                    uint32_t* oc = (uint32_t*)&o;
#pragma unroll
                    for (int q = 0; q < 4; q++) {
                        int ni = ch * 4 + q;
                        float v0 = fmaxf(acc[mi][ni][h * 2 + 0] + bias[ni].x, 0.f);
                        float v1 = fmaxf(acc[mi][ni][h * 2 + 1] + bias[ni].y, 0.f);
                        oc[q] = pack2(v0, v1);
                    }
                    *(uint4*)(rowp + (blockIdx.x * 4 + wn * 2 + ch) * 64) = o;
                }
            }
        }
}

// ---------------- GEMM2: out[tok] += w * (h1b @ W2b^T + b2) -------------------
__global__ __launch_bounds__(256, 2) void gemm2_tc(
    const float* __restrict__ b2, float* __restrict__ out)
{
    extern __shared__ char smem[];
    int e = blockIdx.z;
    int count = min(g_cnt[e], CAP);
    int m0 = blockIdx.y * TM;
    if (m0 >= count) return;
    int n0 = blockIdx.x * TN;

    uint32_t sb = smem_u32(smem);
    int tid = threadIdx.x, wid = tid >> 5, lane = tid & 31;
    int wm = wid >> 1, wn = wid & 1, gid = lane >> 2, tig = lane & 3;

    int arow = tid & 127, sh = tid >> 7;
    int s0 = sh * 2, s1 = s0 + 1;
    int sig = (arow >> 1) & 3;
    uint32_t aoff0 = arow * 64 + ((s0 ^ sig) * 16);
    uint32_t aoff1 = arow * 64 + ((s1 ^ sig) * 16);

    const char* asrc = (const char*)g_h1b + (size_t)(e * CAP + m0 + arow) * 2048;
    const char* bsrc = (const char*)g_w2b + (size_t)(e * HDIM + n0 + arow) * 2048;

    float acc[2][8][4];
#pragma unroll
    for (int mi = 0; mi < 2; mi++)
#pragma unroll
        for (int ni = 0; ni < 8; ni++)
#pragma unroll
            for (int q = 0; q < 4; q++) acc[mi][ni][q] = 0.f;

    STAGE(0, 0); CP_COMMIT();
    STAGE(1, 1); CP_COMMIT();
    STAGE(2, 2); CP_COMMIT();

    for (int c = 0; c < NCH; c++) {
        CP_WAIT2();
        __syncthreads();
        if (c + 3 < NCH) STAGE(c + 3, (c + 3) & 3);
        CP_COMMIT();
        compute_chunk(sb + (c & 3) * STAGE_BYTES, acc, wm, wn, gid, tig);
    }

    // epilogue: out[tok] += w * (acc + b2)
    const float* bb = b2 + e * HDIM + n0 + wn * 64 + tig * 2;
    float2 bias[8];
#pragma unroll
    for (int ni = 0; ni < 8; ni++) bias[ni] = *(const float2*)(bb + ni * 8);

#pragma unroll
    for (int mi = 0; mi < 2; mi++)
#pragma unroll
        for (int h = 0; h < 2; h++) {
            int r = m0 + wm * 32 + mi * 16 + h * 8 + gid;
            if (r < count) {
                int tok = g_tok[e * CAP + r];
                float wv = g_wgt[e * CAP + r];
                float* dp = out + (size_t)tok * HDIM + n0 + wn * 64 + tig * 2;
#pragma unroll
                for (int ni = 0; ni < 8; ni++) {
                    atomicAdd(dp + ni * 8 + 0, (acc[mi][ni][h * 2 + 0] + bias[ni].x) * wv);
                    atomicAdd(dp + ni * 8 + 1, (acc[mi][ni][h * 2 + 1] + bias[ni].y) * wv);
                }
            }
        }
}

// ---------------- launch ------------------------------------------------------
extern "C" void kernel_launch(void* const* d_in, const int* in_sizes, int n_in,
                              void* d_out, int out_size)
{
    const float* x  = (const float*)d_in[0];
    const float* rw = (const float*)d_in[1];
    const float* W1 = (const float*)d_in[2];
    const float* b1 = (const float*)d_in[3];
    const float* W2 = (const float*)d_in[4];
    const float* b2 = (const float*)d_in[5];
    float* out = (float*)d_out;

    void* cnt_addr = nullptr;
    cudaGetSymbolAddress(&cnt_addr, g_cnt);
    cudaMemsetAsync(cnt_addr, 0, NEXP * sizeof(int), 0);

    // residual: out starts as hidden_states; GEMM2 accumulates into it
    cudaMemcpyAsync(out, x, (size_t)T_TOK * HDIM * sizeof(float),
                    cudaMemcpyDeviceToDevice, 0);

    int write_probs = (out_size >= T_TOK * HDIM + T_TOK * NEXP) ? 1 : 0;
    router_kernel<<<T_TOK / 8, 256>>>(x, rw, out, write_probs);

    prepass<<<dim3(T_TOK * NCH / 256, 3), 256>>>(x, W1, W2);

    cudaFuncSetAttribute(gemm1_tc, cudaFuncAttributeMaxDynamicSharedMemorySize, SMEM_BYTES);
    cudaFuncSetAttribute(gemm2_tc, cudaFuncAttributeMaxDynamicSharedMemorySize, SMEM_BYTES);

    dim3 grid(HDIM / TN, CAP / TM, NEXP);
    gemm1_tc<<<grid, 256, SMEM_BYTES>>>(b1);
    gemm2_tc<<<grid, 256, SMEM_BYTES>>>(b2, out);
}

// round 11
// speedup vs baseline: 1.2831x; 1.2831x over previous
#include <cuda_runtime.h>
#include <cuda_bf16.h>
#include <cstdint>
#include <math.h>

// Problem constants
#define T_TOK 8192
#define HDIM  1024
#define NEXP  8
#define CAP   4096

// GEMM tiling: CTA 128x128, 4 warps of 64x64, K-chunk 32.
// Warp-private 3-stage cp.async pipeline: NO CTA barrier in the mainloop.
#define TM 128
#define TN 128
#define KC 32
#define NCH 32
#define WSTG 8192                    // per-warp per-stage: A 4KB + B 4KB
#define NST 3
#define SMEM_BYTES (4 * NST * WSTG)  // 96KB per CTA

// ---------------- scratch (device globals, zero-init at load) ---------------
__device__ int   g_cnt[NEXP];
__device__ int   g_tok[NEXP * CAP];
__device__ float g_wgt[NEXP * CAP];
__device__ uint4 g_xb [(size_t)T_TOK * 128];        // 16MB bf16 permuted x
__device__ uint4 g_w1b[(size_t)NEXP * HDIM * 128];  // 16MB
__device__ uint4 g_w2b[(size_t)NEXP * HDIM * 128];  // 16MB
__device__ uint4 g_h1b[(size_t)NEXP * CAP * 128];   // 64MB bf16 permuted h1

// ---------------- helpers ----------------------------------------------------
__device__ __forceinline__ uint32_t smem_u32(const void* p) {
    uint32_t a;
    asm("{ .reg .u64 t; cvta.to.shared.u64 t, %1; cvt.u32.u64 %0, t; }" : "=r"(a) : "l"(p));
    return a;
}
__device__ __forceinline__ uint32_t pack2(float lo, float hi) {
    uint32_t r;
    asm("cvt.rn.bf16x2.f32 %0, %1, %2;" : "=r"(r) : "f"(hi), "f"(lo));
    return r;
}
__device__ __forceinline__ uint4 lds128(uint32_t addr) {
    uint4 v;
    asm volatile("ld.shared.v4.b32 {%0,%1,%2,%3}, [%4];"
                 : "=r"(v.x), "=r"(v.y), "=r"(v.z), "=r"(v.w) : "r"(addr));
    return v;
}
// L1-cached cp.async (duplicate fetches across warps dedup in L1)
__device__ __forceinline__ void cp16ca(uint32_t dst, const void* src) {
    asm volatile("cp.async.ca.shared.global [%0], [%1], 16;" :: "r"(dst), "l"(src));
}
#define CP_COMMIT() asm volatile("cp.async.commit_group;" ::: "memory")
#define CP_WAIT1()  asm volatile("cp.async.wait_group 1;" ::: "memory")

__device__ __forceinline__ void mma16(float* c,
    uint32_t a0, uint32_t a1, uint32_t a2, uint32_t a3, uint32_t b0, uint32_t b1)
{
    asm volatile(
        "mma.sync.aligned.m16n8k16.row.col.f32.bf16.bf16.f32 "
        "{%0,%1,%2,%3}, {%4,%5,%6,%7}, {%8,%9}, {%0,%1,%2,%3};"
        : "+f"(c[0]), "+f"(c[1]), "+f"(c[2]), "+f"(c[3])
        : "r"(a0), "r"(a1), "r"(a2), "r"(a3), "r"(b0), "r"(b1));
}

// ---------------- prepass: fp32 -> bf16 permuted rows ------------------------
// Permuted chunk row (64B = 16 bf16-pairs): 16B slot s holds pairs {s,s+4,s+8,s+12}
__global__ __launch_bounds__(256) void prepass(
    const float* __restrict__ x, const float* __restrict__ w1,
    const float* __restrict__ w2)
{
    int which = blockIdx.y;
    const float* src = which == 0 ? x : (which == 1 ? w1 : w2);
    uint4* dst = which == 0 ? g_xb : (which == 1 ? g_w1b : g_w2b);
    int idx = blockIdx.x * 256 + threadIdx.x;
    int row = idx >> 5, c = idx & 31;

    const float4* s4 = (const float4*)(src + (size_t)row * HDIM + c * KC);
    float f[32];
#pragma unroll
    for (int i = 0; i < 8; i++) {
        float4 v = s4[i];
        f[4*i] = v.x; f[4*i+1] = v.y; f[4*i+2] = v.z; f[4*i+3] = v.w;
    }
    uint32_t p[16];
#pragma unroll
    for (int P = 0; P < 16; P++) p[P] = pack2(f[2*P], f[2*P+1]);
    uint4* drow = dst + ((size_t)row * 32 + c) * 4;
#pragma unroll
    for (int s = 0; s < 4; s++)
        drow[s] = make_uint4(p[s], p[s+4], p[s+8], p[s+12]);
}

// ---------------- router ------------------------------------------------------
__global__ __launch_bounds__(256) void router_kernel(
    const float* __restrict__ x, const float* __restrict__ rw,
    float* __restrict__ out, int write_probs)
{
    int t = blockIdx.x * 8 + (threadIdx.x >> 5);
    if (t >= T_TOK) return;
    int lane = threadIdx.x & 31;

    float acc[NEXP];
#pragma unroll
    for (int e = 0; e < NEXP; e++) acc[e] = 0.f;
    const float* xp = x + (size_t)t * HDIM;
    for (int i = lane; i < HDIM; i += 32) {
        float xv = xp[i];
#pragma unroll
        for (int e = 0; e < NEXP; e++)
            acc[e] = fmaf(xv, rw[e * HDIM + i], acc[e]);
    }
#pragma unroll
    for (int e = 0; e < NEXP; e++)
#pragma unroll
        for (int off = 16; off; off >>= 1)
            acc[e] += __shfl_xor_sync(0xffffffffu, acc[e], off);

    if (lane == 0) {
        float m = acc[0];
#pragma unroll
        for (int e = 1; e < NEXP; e++) m = fmaxf(m, acc[e]);
        float p[NEXP]; float s = 0.f;
#pragma unroll
        for (int e = 0; e < NEXP; e++) { p[e] = expf(acc[e] - m); s += p[e]; }
        float inv_s = 1.f / s;
#pragma unroll
        for (int e = 0; e < NEXP; e++) p[e] *= inv_s;

        if (write_probs) {
            float* pr = out + (size_t)T_TOK * HDIM + (size_t)t * NEXP;
#pragma unroll
            for (int e = 0; e < NEXP; e++) pr[e] = p[e];
        }
        int i0 = 0;
#pragma unroll
        for (int e = 1; e < NEXP; e++) if (p[e] > p[i0]) i0 = e;
        int i1 = (i0 == 0) ? 1 : 0;
#pragma unroll
        for (int e = 0; e < NEXP; e++) if (e != i0 && p[e] > p[i1]) i1 = e;

        float v0 = p[i0], v1 = p[i1];
        float invw = 1.f / (v0 + v1);
        int pos0 = atomicAdd(&g_cnt[i0], 1);
        if (pos0 < CAP) { g_tok[i0 * CAP + pos0] = t; g_wgt[i0 * CAP + pos0] = v0 * invw; }
        int pos1 = atomicAdd(&g_cnt[i1], 1);
        if (pos1 < CAP) { g_tok[i1 * CAP + pos1] = t; g_wgt[i1 * CAP + pos1] = v1 * invw; }
    }
}

// ---------------- per-chunk compute: 64x64 warp tile, warp-private region ----
// Physical slot of logical slot s in row r is s ^ ((r>>1)&3).
__device__ __forceinline__ void compute_chunk(
    uint32_t wreg, float acc[4][8][4], int gid, int tig)
{
    uint32_t toff = (uint32_t)((tig ^ ((gid >> 1) & 3)) * 16);
    uint4 alo[4], ahi[4];
#pragma unroll
    for (int mi = 0; mi < 4; mi++) {
        uint32_t a0 = wreg + (mi * 16 + gid) * 64 + toff;
        alo[mi] = lds128(a0);
        ahi[mi] = lds128(a0 + 8 * 64);
    }
#pragma unroll
    for (int ni = 0; ni < 8; ni++) {
        uint4 fb = lds128(wreg + 4096 + (ni * 8 + gid) * 64 + toff);
#pragma unroll
        for (int mi = 0; mi < 4; mi++) {
            float* c = acc[mi][ni];
            mma16(c, alo[mi].x, ahi[mi].x, alo[mi].y, ahi[mi].y, fb.x, fb.y);
            mma16(c, alo[mi].z, ahi[mi].z, alo[mi].w, ahi[mi].w, fb.z, fb.w);
        }
    }
}

// stage chunk cc into per-warp stage st.
// Lane l: sl = l&3 (slot), lr = l>>2; covers rows rl = i*8+lr, i=0..7.
// A addr per row from aoffu[i] (u32, covers gather); B affine with i*16384.
#define STAGEP(cc, st) do { \
    uint32_t _d = wbase + (uint32_t)(st) * WSTG + dstoff; \
    uint32_t _g = (uint32_t)(cc) * 64; \
    _Pragma("unroll") \
    for (int i = 0; i < 8; i++) { \
        cp16ca(_d + i * 512,        abase + aoffu[i] + _g); \
        cp16ca(_d + 4096 + i * 512, bbase + i * 16384 + _g); \
    } \
} while (0)

// ---------------- GEMM1: h1b = relu(xb[gather] @ W1b^T + b1) -----------------
__global__ __launch_bounds__(128, 2) void gemm1_tc(const float* __restrict__ b1)
{
    extern __shared__ char smem[];
    int e = blockIdx.z;
    int count = min(g_cnt[e], CAP);
    int m0 = blockIdx.y * TM;
    if (m0 >= count) return;
    int n0 = blockIdx.x * TN;

    uint32_t sb = smem_u32(smem);
    int tid = threadIdx.x, wid = tid >> 5, lane = tid & 31;
    int wm = wid >> 1, wn = wid & 1, gid = lane >> 2, tig = lane & 3;

    // staging geometry (per lane)
    int sl = lane & 3, lr = lane >> 2;
    int sig = (lr >> 1) & 3;
    uint32_t dstoff = (uint32_t)(lr * 64 + ((sl ^ sig) * 16));
    uint32_t wbase = sb + wid * (NST * WSTG);

    const char* abase = (const char*)g_xb + sl * 16;
    const char* bbase = (const char*)g_w1b
        + (size_t)(e * HDIM + n0 + wn * 64 + lr) * 2048 + sl * 16;

    uint32_t aoffu[8];
#pragma unroll
    for (int i = 0; i < 8; i++) {
        int tok = g_tok[e * CAP + m0 + wm * 64 + i * 8 + lr];  // stale -> 0, masked later
        aoffu[i] = (uint32_t)tok * 2048 + (uint32_t)lr * 0;    // token row base
    }

    float acc[4][8][4];
#pragma unroll
    for (int mi = 0; mi < 4; mi++)
#pragma unroll
        for (int ni = 0; ni < 8; ni++)
#pragma unroll
            for (int q = 0; q < 4; q++) acc[mi][ni][q] = 0.f;

    STAGEP(0, 0); CP_COMMIT();
    STAGEP(1, 1); CP_COMMIT();

    int st = 2;
    for (int c = 0; c < NCH; c++) {
        CP_WAIT1();
        __syncwarp();
        if (c + 2 < NCH) { STAGEP(c + 2, st); }
        CP_COMMIT();
        st = (st == 2) ? 0 : st + 1;
        int cur = c % NST;
        compute_chunk(wbase + cur * WSTG, acc, gid, tig);
    }

    // epilogue: relu(acc + b1) -> g_h1b (bf16, permuted rows)
    const float* bb = b1 + e * HDIM + n0 + wn * 64 + tig * 2;
    float2 bias[8];
#pragma unroll
    for (int ni = 0; ni < 8; ni++) bias[ni] = *(const float2*)(bb + ni * 8);

#pragma unroll
    for (int mi = 0; mi < 4; mi++)
#pragma unroll
        for (int ph = 0; ph < 2; ph++) {
            int r = m0 + wm * 64 + mi * 16 + ph * 8 + gid;
            if (r < count) {
                char* rowp = (char*)g_h1b + (size_t)(e * CAP + r) * 2048 + tig * 16;
#pragma unroll
                for (int ch = 0; ch < 2; ch++) {
                    uint4 o;
                    uint32_t* oc = (uint32_t*)&o;
#pragma unroll
                    for (int q = 0; q < 4; q++) {
                        int ni = ch * 4 + q;
                        float v0 = fmaxf(acc[mi][ni][ph * 2 + 0] + bias[ni].x, 0.f);
                        float v1 = fmaxf(acc[mi][ni][ph * 2 + 1] + bias[ni].y, 0.f);
                        oc[q] = pack2(v0, v1);
                    }
                    *(uint4*)(rowp + (blockIdx.x * 4 + wn * 2 + ch) * 64) = o;
                }
            }
        }
}

// ---------------- GEMM2: out[tok] += w * (h1b @ W2b^T + b2) -------------------
__global__ __launch_bounds__(128, 2) void gemm2_tc(
    const float* __restrict__ b2, float* __restrict__ out)
{
    extern __shared__ char smem[];
    int e = blockIdx.z;
    int count = min(g_cnt[e], CAP);
    int m0 = blockIdx.y * TM;
    if (m0 >= count) return;
    int n0 = blockIdx.x * TN;

    uint32_t sb = smem_u32(smem);
    int tid = threadIdx.x, wid = tid >> 5, lane = tid & 31;
    int wm = wid >> 1, wn = wid & 1, gid = lane >> 2, tig = lane & 3;

    int sl = lane & 3, lr = lane >> 2;
    int sig = (lr >> 1) & 3;
    uint32_t dstoff = (uint32_t)(lr * 64 + ((sl ^ sig) * 16));
    uint32_t wbase = sb + wid * (NST * WSTG);

    const char* abase = (const char*)g_h1b
        + (size_t)(e * CAP + m0 + wm * 64 + lr) * 2048 + sl * 16;
    const char* bbase = (const char*)g_w2b
        + (size_t)(e * HDIM + n0 + wn * 64 + lr) * 2048 + sl * 16;

    uint32_t aoffu[8];
#pragma unroll
    for (int i = 0; i < 8; i++) aoffu[i] = (uint32_t)(i * 16384);

    float acc[4][8][4];
#pragma unroll
    for (int mi = 0; mi < 4; mi++)
#pragma unroll
        for (int ni = 0; ni < 8; ni++)
#pragma unroll
            for (int q = 0; q < 4; q++) acc[mi][ni][q] = 0.f;

    STAGEP(0, 0); CP_COMMIT();
    STAGEP(1, 1); CP_COMMIT();

    int st = 2;
    for (int c = 0; c < NCH; c++) {
        CP_WAIT1();
        __syncwarp();
        if (c + 2 < NCH) { STAGEP(c + 2, st); }
        CP_COMMIT();
        st = (st == 2) ? 0 : st + 1;
        int cur = c % NST;
        compute_chunk(wbase + cur * WSTG, acc, gid, tig);
    }

    // epilogue: out[tok] += w * (acc + b2)
    const float* bb = b2 + e * HDIM + n0 + wn * 64 + tig * 2;
    float2 bias[8];
#pragma unroll
    for (int ni = 0; ni < 8; ni++) bias[ni] = *(const float2*)(bb + ni * 8);

#pragma unroll
    for (int mi = 0; mi < 4; mi++)
#pragma unroll
        for (int ph = 0; ph < 2; ph++) {
            int r = m0 + wm * 64 + mi * 16 + ph * 8 + gid;
            if (r < count) {
                int tok = g_tok[e * CAP + r];
                float wv = g_wgt[e * CAP + r];
                float* dp = out + (size_t)tok * HDIM + n0 + wn * 64 + tig * 2;
#pragma unroll
                for (int ni = 0; ni < 8; ni++) {
                    atomicAdd(dp + ni * 8 + 0, (acc[mi][ni][ph * 2 + 0] + bias[ni].x) * wv);
                    atomicAdd(dp + ni * 8 + 1, (acc[mi][ni][ph * 2 + 1] + bias[ni].y) * wv);
                }
            }
        }
}

// ---------------- launch ------------------------------------------------------
extern "C" void kernel_launch(void* const* d_in, const int* in_sizes, int n_in,
                              void* d_out, int out_size)
{
    const float* x  = (const float*)d_in[0];
    const float* rw = (const float*)d_in[1];
    const float* W1 = (const float*)d_in[2];
    const float* b1 = (const float*)d_in[3];
    const float* W2 = (const float*)d_in[4];
    const float* b2 = (const float*)d_in[5];
    float* out = (float*)d_out;

    void* cnt_addr = nullptr;
    cudaGetSymbolAddress(&cnt_addr, g_cnt);
    cudaMemsetAsync(cnt_addr, 0, NEXP * sizeof(int), 0);

    // residual: out starts as hidden_states; GEMM2 accumulates into it
    cudaMemcpyAsync(out, x, (size_t)T_TOK * HDIM * sizeof(float),
                    cudaMemcpyDeviceToDevice, 0);

    int write_probs = (out_size >= T_TOK * HDIM + T_TOK * NEXP) ? 1 : 0;
    router_kernel<<<T_TOK / 8, 256>>>(x, rw, out, write_probs);

    prepass<<<dim3(T_TOK * NCH / 256, 3), 256>>>(x, W1, W2);

    cudaFuncSetAttribute(gemm1_tc, cudaFuncAttributeMaxDynamicSharedMemorySize, SMEM_BYTES);
    cudaFuncSetAttribute(gemm2_tc, cudaFuncAttributeMaxDynamicSharedMemorySize, SMEM_BYTES);

    dim3 grid(HDIM / TN, CAP / TM, NEXP);
    gemm1_tc<<<grid, 128, SMEM_BYTES>>>(b1);
    gemm2_tc<<<grid, 128, SMEM_BYTES>>>(b2, out);
}